// round 4
// baseline (speedup 1.0000x reference)
#include <cuda_runtime.h>
#include <math_constants.h>

#define D 128
#define NEG_SLOPE 0.2f
#define EPS_DEN 1e-16f

#define N_MAX 50048
#define E_MAX 1700000

// ---- static scratch (no device allocations allowed) ----
__device__ __align__(16) float g_h[N_MAX * D];   // projected features
__device__ float g_asrc[N_MAX];
__device__ float g_adst[N_MAX];
__device__ int   g_deg[N_MAX];
__device__ int   g_cursor[N_MAX];
__device__ int   g_rowptr[N_MAX + 1];
__device__ int   g_csr_src[E_MAX];               // src node per CSR slot
__device__ int   g_is64;                         // edge_index dtype flag

// ---------------------------------------------------------------------------
// dtype detection: sample the buffer as int64; any value outside [0,N) => int32
// ---------------------------------------------------------------------------
__global__ void k_detect(const void* ei, int E, int N) {
    __shared__ int bad;
    if (threadIdx.x == 0) bad = 0;
    __syncthreads();
    int samples = min(2 * E, 4096) / 2;   // # of int64 reads (stays in bounds either way)
    const long long* p = (const long long*)ei;
    for (int i = threadIdx.x; i < samples; i += blockDim.x) {
        long long v = p[i];
        if (v < 0 || v >= (long long)N) bad = 1;
    }
    __syncthreads();
    if (threadIdx.x == 0) g_is64 = bad ? 0 : 1;
}

// decode edge e (edges [0,E) real, [E,ET) self-loops), clamped to [0,N)
__device__ __forceinline__ void load_edge(const void* ei, int e, int E, int N,
                                          int& s, int& d) {
    if (e < E) {
        if (g_is64) {
            s = (int)((const long long*)ei)[e];
            d = (int)((const long long*)ei)[E + e];
        } else {
            s = ((const int*)ei)[e];
            d = ((const int*)ei)[E + e];
        }
    } else {
        s = d = e - E;
    }
    s = min(max(s, 0), N - 1);
    d = min(max(d, 0), N - 1);
}

// ---------------------------------------------------------------------------
// zero degree + cursor
// ---------------------------------------------------------------------------
__global__ void k_zero(int N) {
    int i = blockIdx.x * blockDim.x + threadIdx.x;
    if (i < N) {
        g_deg[i]    = 0;
        g_cursor[i] = 0;
    }
}

// ---------------------------------------------------------------------------
// GEMM: h = x @ W   (x: [N,128], W: [128,128])
// ---------------------------------------------------------------------------
__global__ __launch_bounds__(256) void k_gemm(const float* __restrict__ x,
                                              const float* __restrict__ W,
                                              int N) {
    __shared__ __align__(16) float xs[128][33];   // [row][k] padded
    __shared__ __align__(16) float ws[32][128];   // [k][col]

    const int tid = threadIdx.x;
    const int tx  = tid & 15;
    const int ty  = tid >> 4;
    const int rowBase = blockIdx.x * 128;

    float acc[8][8];
#pragma unroll
    for (int i = 0; i < 8; i++)
#pragma unroll
        for (int j = 0; j < 8; j++) acc[i][j] = 0.f;

    for (int k0 = 0; k0 < 128; k0 += 32) {
#pragma unroll
        for (int t = tid; t < 1024; t += 256) {
            int r  = t >> 3;
            int kq = t & 7;
            float4 v = make_float4(0.f, 0.f, 0.f, 0.f);
            int row = rowBase + r;
            if (row < N) v = *(const float4*)&x[row * 128 + k0 + kq * 4];
            xs[r][kq * 4 + 0] = v.x;
            xs[r][kq * 4 + 1] = v.y;
            xs[r][kq * 4 + 2] = v.z;
            xs[r][kq * 4 + 3] = v.w;
        }
#pragma unroll
        for (int t = tid; t < 1024; t += 256) {
            int kk = t >> 5;
            int cq = t & 31;
            *(float4*)&ws[kk][cq * 4] = *(const float4*)&W[(k0 + kk) * 128 + cq * 4];
        }
        __syncthreads();

#pragma unroll
        for (int kk = 0; kk < 32; kk++) {
            float a[8], b[8];
#pragma unroll
            for (int i = 0; i < 8; i++) a[i] = xs[ty * 8 + i][kk];
#pragma unroll
            for (int j = 0; j < 8; j++) b[j] = ws[kk][tx * 8 + j];
#pragma unroll
            for (int i = 0; i < 8; i++)
#pragma unroll
                for (int j = 0; j < 8; j++) acc[i][j] = fmaf(a[i], b[j], acc[i][j]);
        }
        __syncthreads();
    }

#pragma unroll
    for (int i = 0; i < 8; i++) {
        int row = rowBase + ty * 8 + i;
        if (row < N) {
#pragma unroll
            for (int j = 0; j < 8; j += 4) {
                float4 v = make_float4(acc[i][j], acc[i][j + 1], acc[i][j + 2], acc[i][j + 3]);
                *(float4*)&g_h[row * 128 + tx * 8 + j] = v;
            }
        }
    }
}

// ---------------------------------------------------------------------------
// per-node attention scores (one warp per node)
// ---------------------------------------------------------------------------
__global__ void k_scores(const float* __restrict__ att_s,
                         const float* __restrict__ att_d, int N) {
    int gt   = blockIdx.x * blockDim.x + threadIdx.x;
    int node = gt >> 5;
    int lane = gt & 31;
    if (node >= N) return;

    float4 hv = *(const float4*)&g_h[node * 128 + lane * 4];
    float4 s4 = *(const float4*)&att_s[lane * 4];
    float4 d4 = *(const float4*)&att_d[lane * 4];

    float s = hv.x * s4.x + hv.y * s4.y + hv.z * s4.z + hv.w * s4.w;
    float d = hv.x * d4.x + hv.y * d4.y + hv.z * d4.z + hv.w * d4.w;

#pragma unroll
    for (int o = 16; o > 0; o >>= 1) {
        s += __shfl_xor_sync(0xffffffffu, s, o);
        d += __shfl_xor_sync(0xffffffffu, d, o);
    }
    if (lane == 0) {
        g_asrc[node] = s;
        g_adst[node] = d;
    }
}

// ---------------------------------------------------------------------------
// degree histogram over destinations
// ---------------------------------------------------------------------------
__global__ void k_count(const void* __restrict__ ei, int E, int ET, int N) {
    int e = blockIdx.x * blockDim.x + threadIdx.x;
    if (e >= ET) return;
    int s, d;
    load_edge(ei, e, E, N, s, d);
    atomicAdd(&g_deg[d], 1);
}

// ---------------------------------------------------------------------------
// single-block exclusive scan over g_deg -> g_rowptr
// ---------------------------------------------------------------------------
__global__ __launch_bounds__(1024) void k_scan(int N) {
    __shared__ int ssum[1024];
    const int t = threadIdx.x;
    const int chunk = (N + 1023) / 1024;
    const int beg = t * chunk;
    const int end = min(beg + chunk, N);

    int sum = 0;
    for (int i = beg; i < end; i++) sum += g_deg[i];
    ssum[t] = sum;
    __syncthreads();

    for (int s = 1; s < 1024; s <<= 1) {
        int v = (t >= s) ? ssum[t - s] : 0;
        __syncthreads();
        ssum[t] += v;
        __syncthreads();
    }

    int off = ssum[t] - sum;
    for (int i = beg; i < end; i++) {
        g_rowptr[i] = off;
        off += g_deg[i];
    }
    if (t == 1023) g_rowptr[N] = ssum[1023];
}

// ---------------------------------------------------------------------------
// CSR fill: bucket edges by dst
// ---------------------------------------------------------------------------
__global__ void k_fill(const void* __restrict__ ei, int E, int ET, int N) {
    int e = blockIdx.x * blockDim.x + threadIdx.x;
    if (e >= ET) return;
    int s, d;
    load_edge(ei, e, E, N, s, d);
    int pos = atomicAdd(&g_cursor[d], 1);
    g_csr_src[g_rowptr[d] + pos] = s;
}

// ---------------------------------------------------------------------------
// fused segment softmax + aggregation: one warp per destination node
// ---------------------------------------------------------------------------
__global__ void k_agg(float* __restrict__ out, int N) {
    int gt   = blockIdx.x * blockDim.x + threadIdx.x;
    int node = gt >> 5;
    int lane = gt & 31;
    if (node >= N) return;

    const int beg = g_rowptr[node];
    const int end = g_rowptr[node + 1];
    const float adst = g_adst[node];

    // pass 1: segment max
    float m = -CUDART_INF_F;
    for (int j = beg + lane; j < end; j += 32) {
        int s = g_csr_src[j];
        float al = g_asrc[s] + adst;
        al = (al > 0.f) ? al : NEG_SLOPE * al;
        m = fmaxf(m, al);
    }
#pragma unroll
    for (int o = 16; o > 0; o >>= 1)
        m = fmaxf(m, __shfl_xor_sync(0xffffffffu, m, o));
    if (!isfinite(m)) m = 0.0f;

    // pass 2: denom
    float ssum = 0.f;
    for (int j = beg + lane; j < end; j += 32) {
        int s = g_csr_src[j];
        float al = g_asrc[s] + adst;
        al = (al > 0.f) ? al : NEG_SLOPE * al;
        ssum += __expf(al - m);
    }
#pragma unroll
    for (int o = 16; o > 0; o >>= 1)
        ssum += __shfl_xor_sync(0xffffffffu, ssum, o);
    const float inv = 1.0f / (ssum + EPS_DEN);

    // pass 3: weighted aggregation; srcs/coefs staged via shuffle broadcast
    float ax = 0.f, ay = 0.f, az = 0.f, aw = 0.f;
    for (int j0 = beg; j0 < end; j0 += 32) {
        int j = j0 + lane;
        int s = 0;
        float coef = 0.f;
        if (j < end) {
            s = g_csr_src[j];
            float al = g_asrc[s] + adst;
            al = (al > 0.f) ? al : NEG_SLOPE * al;
            coef = __expf(al - m) * inv;
        }
        int cnt = min(32, end - j0);
        for (int t = 0; t < cnt; t++) {
            int   ss = __shfl_sync(0xffffffffu, s, t);
            float cc = __shfl_sync(0xffffffffu, coef, t);
            float4 hv = *(const float4*)&g_h[ss * 128 + lane * 4];
            ax = fmaf(hv.x, cc, ax);
            ay = fmaf(hv.y, cc, ay);
            az = fmaf(hv.z, cc, az);
            aw = fmaf(hv.w, cc, aw);
        }
    }

    *(float4*)&out[node * 128 + lane * 4] = make_float4(ax, ay, az, aw);
}

// ---------------------------------------------------------------------------
extern "C" void kernel_launch(void* const* d_in, const int* in_sizes, int n_in,
                              void* d_out, int out_size) {
    const float* x     = (const float*)d_in[0];
    const void*  ei    = d_in[1];
    const float* W     = (const float*)d_in[2];
    const float* att_s = (const float*)d_in[3];
    const float* att_d = (const float*)d_in[4];
    float*       out   = (float*)d_out;

    const int N  = in_sizes[0] / D;
    const int E  = in_sizes[1] / 2;
    const int ET = E + N;

    k_detect<<<1, 256>>>(ei, E, N);
    k_zero<<<(N + 255) / 256, 256>>>(N);
    k_gemm<<<(N + 127) / 128, 256>>>(x, W, N);
    k_scores<<<(N * 32 + 255) / 256, 256>>>(att_s, att_d, N);
    k_count<<<(ET + 255) / 256, 256>>>(ei, E, ET, N);
    k_scan<<<1, 1024>>>(N);
    k_fill<<<(ET + 255) / 256, 256>>>(ei, E, ET, N);
    {
        long long threads = (long long)N * 32;
        int blocks = (int)((threads + 255) / 256);
        k_agg<<<blocks, 256>>>(out, N);
    }
}

// round 5
// speedup vs baseline: 1.0613x; 1.0613x over previous
#include <cuda_runtime.h>
#include <math_constants.h>

#define D 128
#define NEG_SLOPE 0.2f
#define EPS_DEN 1e-16f

#define N_MAX 50048
#define E_MAX 1700000

// ---- static scratch (no device allocations allowed) ----
__device__ __align__(16) float g_h[N_MAX * D];   // projected features
__device__ float g_asrc[N_MAX];
__device__ float g_adst[N_MAX];
__device__ int   g_deg[N_MAX];
__device__ int   g_cursor[N_MAX];
__device__ int   g_rowptr[N_MAX + 1];
__device__ __align__(16) int2 g_csr[E_MAX];      // {src, float_bits(alpha)} per CSR slot
__device__ int   g_is64;                         // edge_index dtype flag

// ---------------------------------------------------------------------------
// prep: zero deg/cursor everywhere; block 0 also detects edge dtype
// (sample buffer as int64; any value outside [0,N) => int32)
// ---------------------------------------------------------------------------
__global__ void k_prep(const void* ei, int E, int N) {
    int i = blockIdx.x * blockDim.x + threadIdx.x;
    if (i < N) {
        g_deg[i]    = 0;
        g_cursor[i] = 0;
    }
    if (blockIdx.x == 0) {
        __shared__ int bad;
        if (threadIdx.x == 0) bad = 0;
        __syncthreads();
        int samples = min(2 * E, 4096) / 2;
        const long long* p = (const long long*)ei;
        for (int t = threadIdx.x; t < samples; t += blockDim.x) {
            long long v = p[t];
            if (v < 0 || v >= (long long)N) bad = 1;
        }
        __syncthreads();
        if (threadIdx.x == 0) g_is64 = bad ? 0 : 1;
    }
}

// decode edge e (edges [0,E) real, [E,ET) self-loops), clamped to [0,N)
__device__ __forceinline__ void load_edge(const void* ei, int e, int E, int N,
                                          int& s, int& d) {
    if (e < E) {
        if (g_is64) {
            s = (int)((const long long*)ei)[e];
            d = (int)((const long long*)ei)[E + e];
        } else {
            s = ((const int*)ei)[e];
            d = ((const int*)ei)[E + e];
        }
    } else {
        s = d = e - E;
    }
    s = min(max(s, 0), N - 1);
    d = min(max(d, 0), N - 1);
}

__device__ __forceinline__ int load_dst(const void* ei, int e, int E, int N) {
    int d;
    if (e < E) {
        d = g_is64 ? (int)((const long long*)ei)[E + e] : ((const int*)ei)[E + e];
    } else {
        d = e - E;
    }
    return min(max(d, 0), N - 1);
}

// ---------------------------------------------------------------------------
// GEMM: h = x @ W  with fused per-node score epilogue
//   a_src[n] = h[n]·att_src, a_dst[n] = h[n]·att_dst
// block = 256 threads computes a 128x128 tile; 8x8 register microtile.
// ---------------------------------------------------------------------------
__global__ __launch_bounds__(256) void k_gemm(const float* __restrict__ x,
                                              const float* __restrict__ W,
                                              const float* __restrict__ att_s,
                                              const float* __restrict__ att_d,
                                              int N) {
    __shared__ __align__(16) float xs[128][33];   // [row][k] padded
    __shared__ __align__(16) float ws[32][128];   // [k][col]
    __shared__ float ps[128][17];                 // score partials (src)
    __shared__ float pd[128][17];                 // score partials (dst)

    const int tid = threadIdx.x;
    const int tx  = tid & 15;
    const int ty  = tid >> 4;
    const int rowBase = blockIdx.x * 128;

    float acc[8][8];
#pragma unroll
    for (int i = 0; i < 8; i++)
#pragma unroll
        for (int j = 0; j < 8; j++) acc[i][j] = 0.f;

    for (int k0 = 0; k0 < 128; k0 += 32) {
#pragma unroll
        for (int t = tid; t < 1024; t += 256) {
            int r  = t >> 3;
            int kq = t & 7;
            float4 v = make_float4(0.f, 0.f, 0.f, 0.f);
            int row = rowBase + r;
            if (row < N) v = *(const float4*)&x[row * 128 + k0 + kq * 4];
            xs[r][kq * 4 + 0] = v.x;
            xs[r][kq * 4 + 1] = v.y;
            xs[r][kq * 4 + 2] = v.z;
            xs[r][kq * 4 + 3] = v.w;
        }
#pragma unroll
        for (int t = tid; t < 1024; t += 256) {
            int kk = t >> 5;
            int cq = t & 31;
            *(float4*)&ws[kk][cq * 4] = *(const float4*)&W[(k0 + kk) * 128 + cq * 4];
        }
        __syncthreads();

#pragma unroll
        for (int kk = 0; kk < 32; kk++) {
            float a[8], b[8];
#pragma unroll
            for (int i = 0; i < 8; i++) a[i] = xs[ty * 8 + i][kk];
#pragma unroll
            for (int j = 0; j < 8; j++) b[j] = ws[kk][tx * 8 + j];
#pragma unroll
            for (int i = 0; i < 8; i++)
#pragma unroll
                for (int j = 0; j < 8; j++) acc[i][j] = fmaf(a[i], b[j], acc[i][j]);
        }
        __syncthreads();
    }

    // store h tile
#pragma unroll
    for (int i = 0; i < 8; i++) {
        int row = rowBase + ty * 8 + i;
        if (row < N) {
#pragma unroll
            for (int j = 0; j < 8; j += 4) {
                float4 v = make_float4(acc[i][j], acc[i][j + 1], acc[i][j + 2], acc[i][j + 3]);
                *(float4*)&g_h[row * 128 + tx * 8 + j] = v;
            }
        }
    }

    // fused score epilogue: partial dot products from live accumulators
    float as[8], ad[8];
#pragma unroll
    for (int j = 0; j < 8; j++) {
        as[j] = att_s[tx * 8 + j];
        ad[j] = att_d[tx * 8 + j];
    }
#pragma unroll
    for (int i = 0; i < 8; i++) {
        float s = 0.f, d = 0.f;
#pragma unroll
        for (int j = 0; j < 8; j++) {
            s = fmaf(acc[i][j], as[j], s);
            d = fmaf(acc[i][j], ad[j], d);
        }
        ps[ty * 8 + i][tx] = s;
        pd[ty * 8 + i][tx] = d;
    }
    __syncthreads();
    if (tid < 128) {
        int row = rowBase + tid;
        if (row < N) {
            float s = 0.f, d = 0.f;
#pragma unroll
            for (int k = 0; k < 16; k++) {
                s += ps[tid][k];
                d += pd[tid][k];
            }
            g_asrc[row] = s;
            g_adst[row] = d;
        }
    }
}

// ---------------------------------------------------------------------------
// degree histogram over destinations (dst half only)
// ---------------------------------------------------------------------------
__global__ void k_count(const void* __restrict__ ei, int E, int ET, int N) {
    int e = blockIdx.x * blockDim.x + threadIdx.x;
    if (e >= ET) return;
    atomicAdd(&g_deg[load_dst(ei, e, E, N)], 1);
}

// ---------------------------------------------------------------------------
// single-block exclusive scan over g_deg -> g_rowptr
// ---------------------------------------------------------------------------
__global__ __launch_bounds__(1024) void k_scan(int N) {
    __shared__ int ssum[1024];
    const int t = threadIdx.x;
    const int chunk = (N + 1023) / 1024;
    const int beg = t * chunk;
    const int end = min(beg + chunk, N);

    int sum = 0;
    for (int i = beg; i < end; i++) sum += g_deg[i];
    ssum[t] = sum;
    __syncthreads();

    for (int s = 1; s < 1024; s <<= 1) {
        int v = (t >= s) ? ssum[t - s] : 0;
        __syncthreads();
        ssum[t] += v;
        __syncthreads();
    }

    int off = ssum[t] - sum;
    for (int i = beg; i < end; i++) {
        g_rowptr[i] = off;
        off += g_deg[i];
    }
    if (t == 1023) g_rowptr[N] = ssum[1023];
}

// ---------------------------------------------------------------------------
// CSR fill: bucket edges by dst; precompute alpha = leaky(a_src[s]+a_dst[d])
// ---------------------------------------------------------------------------
__global__ void k_fill(const void* __restrict__ ei, int E, int ET, int N) {
    int e = blockIdx.x * blockDim.x + threadIdx.x;
    if (e >= ET) return;
    int s, d;
    load_edge(ei, e, E, N, s, d);
    float al = g_asrc[s] + g_adst[d];
    al = (al > 0.f) ? al : NEG_SLOPE * al;
    int pos = atomicAdd(&g_cursor[d], 1);
    g_csr[g_rowptr[d] + pos] = make_int2(s, __float_as_int(al));
}

// ---------------------------------------------------------------------------
// fused segment softmax + aggregation: one warp per destination node.
// alpha precomputed in CSR record -> all passes stream sequentially.
// ---------------------------------------------------------------------------
__global__ void k_agg(float* __restrict__ out, int N) {
    int gt   = blockIdx.x * blockDim.x + threadIdx.x;
    int node = gt >> 5;
    int lane = gt & 31;
    if (node >= N) return;

    const int beg = g_rowptr[node];
    const int end = g_rowptr[node + 1];

    // pass 1: segment max
    float m = -CUDART_INF_F;
    for (int j = beg + lane; j < end; j += 32)
        m = fmaxf(m, __int_as_float(g_csr[j].y));
#pragma unroll
    for (int o = 16; o > 0; o >>= 1)
        m = fmaxf(m, __shfl_xor_sync(0xffffffffu, m, o));
    if (!isfinite(m)) m = 0.0f;

    // pass 2: denom (L1-hot reload)
    float ssum = 0.f;
    for (int j = beg + lane; j < end; j += 32)
        ssum += __expf(__int_as_float(g_csr[j].y) - m);
#pragma unroll
    for (int o = 16; o > 0; o >>= 1)
        ssum += __shfl_xor_sync(0xffffffffu, ssum, o);
    const float inv = 1.0f / (ssum + EPS_DEN);

    // pass 3: weighted aggregation; srcs/coefs staged via shuffle broadcast
    float ax = 0.f, ay = 0.f, az = 0.f, aw = 0.f;
    for (int j0 = beg; j0 < end; j0 += 32) {
        int j = j0 + lane;
        int s = 0;
        float coef = 0.f;
        if (j < end) {
            int2 p = g_csr[j];
            s = p.x;
            coef = __expf(__int_as_float(p.y) - m) * inv;
        }
        int cnt = min(32, end - j0);
        for (int t = 0; t < cnt; t++) {
            int   ss = __shfl_sync(0xffffffffu, s, t);
            float cc = __shfl_sync(0xffffffffu, coef, t);
            float4 hv = *(const float4*)&g_h[ss * 128 + lane * 4];
            ax = fmaf(hv.x, cc, ax);
            ay = fmaf(hv.y, cc, ay);
            az = fmaf(hv.z, cc, az);
            aw = fmaf(hv.w, cc, aw);
        }
    }

    *(float4*)&out[node * 128 + lane * 4] = make_float4(ax, ay, az, aw);
}

// ---------------------------------------------------------------------------
extern "C" void kernel_launch(void* const* d_in, const int* in_sizes, int n_in,
                              void* d_out, int out_size) {
    const float* x     = (const float*)d_in[0];
    const void*  ei    = d_in[1];
    const float* W     = (const float*)d_in[2];
    const float* att_s = (const float*)d_in[3];
    const float* att_d = (const float*)d_in[4];
    float*       out   = (float*)d_out;

    const int N  = in_sizes[0] / D;
    const int E  = in_sizes[1] / 2;
    const int ET = E + N;

    k_prep<<<(N + 255) / 256, 256>>>(ei, E, N);
    k_gemm<<<(N + 127) / 128, 256>>>(x, W, att_s, att_d, N);
    k_count<<<(ET + 255) / 256, 256>>>(ei, E, ET, N);
    k_scan<<<1, 1024>>>(N);
    k_fill<<<(ET + 255) / 256, 256>>>(ei, E, ET, N);
    {
        long long threads = (long long)N * 32;
        int blocks = (int)((threads + 255) / 256);
        k_agg<<<blocks, 256>>>(out, N);
    }
}

// round 6
// speedup vs baseline: 1.3144x; 1.2385x over previous
#include <cuda_runtime.h>
#include <math_constants.h>

#define D 128
#define NEG_SLOPE 0.2f
#define EPS_DEN 1e-16f

#define N_MAX 50048
#define E_MAX 1700000
#define SCAN_B 1024
#define NB_MAX 64

// ---- static scratch (no device allocations allowed) ----
__device__ __align__(16) float g_h[N_MAX * D];   // projected features
__device__ float g_asrc[N_MAX];
__device__ float g_adst[N_MAX];
__device__ int   g_deg[N_MAX];
__device__ int   g_cursor[N_MAX];
__device__ int   g_rowptr[N_MAX + 1];
__device__ int   g_bsum[NB_MAX];
__device__ int   g_boff[NB_MAX];
__device__ __align__(16) int2 g_csr[E_MAX];      // {src, float_bits(alpha)} per CSR slot
__device__ int   g_is64;                         // edge_index dtype flag

// ---------------------------------------------------------------------------
// prep: zero deg/cursor; block 0 detects edge dtype
// ---------------------------------------------------------------------------
__global__ void k_prep(const void* ei, int E, int N) {
    int i = blockIdx.x * blockDim.x + threadIdx.x;
    if (i < N) {
        g_deg[i]    = 0;
        g_cursor[i] = 0;
    }
    if (blockIdx.x == 0) {
        __shared__ int bad;
        if (threadIdx.x == 0) bad = 0;
        __syncthreads();
        int samples = min(2 * E, 4096) / 2;
        const long long* p = (const long long*)ei;
        for (int t = threadIdx.x; t < samples; t += blockDim.x) {
            long long v = p[t];
            if (v < 0 || v >= (long long)N) bad = 1;
        }
        __syncthreads();
        if (threadIdx.x == 0) g_is64 = bad ? 0 : 1;
    }
}

// decode edge e (edges [0,E) real, [E,ET) self-loops), clamped to [0,N)
__device__ __forceinline__ void load_edge(const void* ei, int e, int E, int N,
                                          int& s, int& d) {
    if (e < E) {
        if (g_is64) {
            s = (int)((const long long*)ei)[e];
            d = (int)((const long long*)ei)[E + e];
        } else {
            s = ((const int*)ei)[e];
            d = ((const int*)ei)[E + e];
        }
    } else {
        s = d = e - E;
    }
    s = min(max(s, 0), N - 1);
    d = min(max(d, 0), N - 1);
}

__device__ __forceinline__ int load_dst(const void* ei, int e, int E, int N) {
    int d;
    if (e < E) {
        d = g_is64 ? (int)((const long long*)ei)[E + e] : ((const int*)ei)[E + e];
    } else {
        d = e - E;
    }
    return min(max(d, 0), N - 1);
}

// ---------------------------------------------------------------------------
// GEMM: h = x @ W  with fused per-node score epilogue
// ---------------------------------------------------------------------------
__global__ __launch_bounds__(256) void k_gemm(const float* __restrict__ x,
                                              const float* __restrict__ W,
                                              const float* __restrict__ att_s,
                                              const float* __restrict__ att_d,
                                              int N) {
    __shared__ __align__(16) float xs[128][33];
    __shared__ __align__(16) float ws[32][128];
    __shared__ float ps[128][17];
    __shared__ float pd[128][17];

    const int tid = threadIdx.x;
    const int tx  = tid & 15;
    const int ty  = tid >> 4;
    const int rowBase = blockIdx.x * 128;

    float acc[8][8];
#pragma unroll
    for (int i = 0; i < 8; i++)
#pragma unroll
        for (int j = 0; j < 8; j++) acc[i][j] = 0.f;

    for (int k0 = 0; k0 < 128; k0 += 32) {
#pragma unroll
        for (int t = tid; t < 1024; t += 256) {
            int r  = t >> 3;
            int kq = t & 7;
            float4 v = make_float4(0.f, 0.f, 0.f, 0.f);
            int row = rowBase + r;
            if (row < N) v = *(const float4*)&x[row * 128 + k0 + kq * 4];
            xs[r][kq * 4 + 0] = v.x;
            xs[r][kq * 4 + 1] = v.y;
            xs[r][kq * 4 + 2] = v.z;
            xs[r][kq * 4 + 3] = v.w;
        }
#pragma unroll
        for (int t = tid; t < 1024; t += 256) {
            int kk = t >> 5;
            int cq = t & 31;
            *(float4*)&ws[kk][cq * 4] = *(const float4*)&W[(k0 + kk) * 128 + cq * 4];
        }
        __syncthreads();

#pragma unroll
        for (int kk = 0; kk < 32; kk++) {
            float a[8], b[8];
#pragma unroll
            for (int i = 0; i < 8; i++) a[i] = xs[ty * 8 + i][kk];
#pragma unroll
            for (int j = 0; j < 8; j++) b[j] = ws[kk][tx * 8 + j];
#pragma unroll
            for (int i = 0; i < 8; i++)
#pragma unroll
                for (int j = 0; j < 8; j++) acc[i][j] = fmaf(a[i], b[j], acc[i][j]);
        }
        __syncthreads();
    }

#pragma unroll
    for (int i = 0; i < 8; i++) {
        int row = rowBase + ty * 8 + i;
        if (row < N) {
#pragma unroll
            for (int j = 0; j < 8; j += 4) {
                float4 v = make_float4(acc[i][j], acc[i][j + 1], acc[i][j + 2], acc[i][j + 3]);
                *(float4*)&g_h[row * 128 + tx * 8 + j] = v;
            }
        }
    }

    // fused score epilogue
    float as[8], ad[8];
#pragma unroll
    for (int j = 0; j < 8; j++) {
        as[j] = att_s[tx * 8 + j];
        ad[j] = att_d[tx * 8 + j];
    }
#pragma unroll
    for (int i = 0; i < 8; i++) {
        float s = 0.f, d = 0.f;
#pragma unroll
        for (int j = 0; j < 8; j++) {
            s = fmaf(acc[i][j], as[j], s);
            d = fmaf(acc[i][j], ad[j], d);
        }
        ps[ty * 8 + i][tx] = s;
        pd[ty * 8 + i][tx] = d;
    }
    __syncthreads();
    if (tid < 128) {
        int row = rowBase + tid;
        if (row < N) {
            float s = 0.f, d = 0.f;
#pragma unroll
            for (int k = 0; k < 16; k++) {
                s += ps[tid][k];
                d += pd[tid][k];
            }
            g_asrc[row] = s;
            g_adst[row] = d;
        }
    }
}

// ---------------------------------------------------------------------------
// degree histogram over destinations (dst half only)
// ---------------------------------------------------------------------------
__global__ void k_count(const void* __restrict__ ei, int E, int ET, int N) {
    int e = blockIdx.x * blockDim.x + threadIdx.x;
    if (e >= ET) return;
    atomicAdd(&g_deg[load_dst(ei, e, E, N)], 1);
}

// ---------------------------------------------------------------------------
// multi-block exclusive scan: A (per-block scan) -> B (block totals) -> C (add)
// ---------------------------------------------------------------------------
__device__ __forceinline__ int block_incl_scan(int v, int tid) {
    const int lane = tid & 31;
    const int wid  = tid >> 5;
    __shared__ int wsum[32];

    int x = v;
#pragma unroll
    for (int o = 1; o < 32; o <<= 1) {
        int y = __shfl_up_sync(0xffffffffu, x, o);
        if (lane >= o) x += y;
    }
    if (lane == 31) wsum[wid] = x;
    __syncthreads();
    if (wid == 0) {
        int w = wsum[lane];
#pragma unroll
        for (int o = 1; o < 32; o <<= 1) {
            int y = __shfl_up_sync(0xffffffffu, w, o);
            if (lane >= o) w += y;
        }
        wsum[lane] = w;
    }
    __syncthreads();
    return x + (wid > 0 ? wsum[wid - 1] : 0);   // inclusive scan of v
}

__global__ __launch_bounds__(SCAN_B) void k_scanA(int N) {
    int i = blockIdx.x * SCAN_B + threadIdx.x;
    int v = (i < N) ? g_deg[i] : 0;
    int incl = block_incl_scan(v, threadIdx.x);
    if (i < N) g_rowptr[i] = incl - v;                       // local exclusive
    if (threadIdx.x == SCAN_B - 1) g_bsum[blockIdx.x] = incl; // block total
}

__global__ __launch_bounds__(NB_MAX) void k_scanB(int nb) {
    int t = threadIdx.x;
    int v = (t < nb) ? g_bsum[t] : 0;
    int x = v;
#pragma unroll
    for (int o = 1; o < NB_MAX; o <<= 1) {
        int y = __shfl_up_sync(0xffffffffu, x, o);   // NB_MAX<=64: two warps
        if ((t & 31) >= o) x += y;
    }
    // cross-warp fixup for 2 warps
    __shared__ int w0;
    if (t == 31) w0 = x;
    __syncthreads();
    if (t >= 32) x += w0;
    if (t < nb) g_boff[t] = x - v;   // exclusive block offsets
    if (t == nb - 1) g_boff[NB_MAX - 1] = x;  // total stashed at tail (unused if nb==NB_MAX)
}

__global__ __launch_bounds__(SCAN_B) void k_scanC(int N, int ET, int nb) {
    int i = blockIdx.x * SCAN_B + threadIdx.x;
    int off = g_boff[blockIdx.x];
    if (i < N) g_rowptr[i] += off;
    if (i == N - 1) g_rowptr[N] = ET;   // total is known statically
}

// ---------------------------------------------------------------------------
// CSR fill: bucket edges by dst; precompute alpha = leaky(a_src[s]+a_dst[d])
// ---------------------------------------------------------------------------
__global__ void k_fill(const void* __restrict__ ei, int E, int ET, int N) {
    int e = blockIdx.x * blockDim.x + threadIdx.x;
    if (e >= ET) return;
    int s, d;
    load_edge(ei, e, E, N, s, d);
    float al = g_asrc[s] + g_adst[d];
    al = (al > 0.f) ? al : NEG_SLOPE * al;
    int pos = atomicAdd(&g_cursor[d], 1);
    g_csr[g_rowptr[d] + pos] = make_int2(s, __float_as_int(al));
}

// ---------------------------------------------------------------------------
// fused segment softmax + aggregation: one warp per destination node
// ---------------------------------------------------------------------------
__global__ void k_agg(float* __restrict__ out, int N) {
    int gt   = blockIdx.x * blockDim.x + threadIdx.x;
    int node = gt >> 5;
    int lane = gt & 31;
    if (node >= N) return;

    const int beg = g_rowptr[node];
    const int end = g_rowptr[node + 1];

    float m = -CUDART_INF_F;
    for (int j = beg + lane; j < end; j += 32)
        m = fmaxf(m, __int_as_float(g_csr[j].y));
#pragma unroll
    for (int o = 16; o > 0; o >>= 1)
        m = fmaxf(m, __shfl_xor_sync(0xffffffffu, m, o));
    if (!isfinite(m)) m = 0.0f;

    float ssum = 0.f;
    for (int j = beg + lane; j < end; j += 32)
        ssum += __expf(__int_as_float(g_csr[j].y) - m);
#pragma unroll
    for (int o = 16; o > 0; o >>= 1)
        ssum += __shfl_xor_sync(0xffffffffu, ssum, o);
    const float inv = 1.0f / (ssum + EPS_DEN);

    float ax = 0.f, ay = 0.f, az = 0.f, aw = 0.f;
    for (int j0 = beg; j0 < end; j0 += 32) {
        int j = j0 + lane;
        int s = 0;
        float coef = 0.f;
        if (j < end) {
            int2 p = g_csr[j];
            s = p.x;
            coef = __expf(__int_as_float(p.y) - m) * inv;
        }
        int cnt = min(32, end - j0);
        for (int t = 0; t < cnt; t++) {
            int   ss = __shfl_sync(0xffffffffu, s, t);
            float cc = __shfl_sync(0xffffffffu, coef, t);
            float4 hv = *(const float4*)&g_h[ss * 128 + lane * 4];
            ax = fmaf(hv.x, cc, ax);
            ay = fmaf(hv.y, cc, ay);
            az = fmaf(hv.z, cc, az);
            aw = fmaf(hv.w, cc, aw);
        }
    }

    *(float4*)&out[node * 128 + lane * 4] = make_float4(ax, ay, az, aw);
}

// ---------------------------------------------------------------------------
extern "C" void kernel_launch(void* const* d_in, const int* in_sizes, int n_in,
                              void* d_out, int out_size) {
    const float* x     = (const float*)d_in[0];
    const void*  ei    = d_in[1];
    const float* W     = (const float*)d_in[2];
    const float* att_s = (const float*)d_in[3];
    const float* att_d = (const float*)d_in[4];
    float*       out   = (float*)d_out;

    const int N  = in_sizes[0] / D;
    const int E  = in_sizes[1] / 2;
    const int ET = E + N;
    const int nb = (N + SCAN_B - 1) / SCAN_B;

    k_prep<<<(N + 255) / 256, 256>>>(ei, E, N);
    k_gemm<<<(N + 127) / 128, 256>>>(x, W, att_s, att_d, N);
    k_count<<<(ET + 255) / 256, 256>>>(ei, E, ET, N);
    k_scanA<<<nb, SCAN_B>>>(N);
    k_scanB<<<1, NB_MAX>>>(nb);
    k_scanC<<<nb, SCAN_B>>>(N, ET, nb);
    k_fill<<<(ET + 255) / 256, 256>>>(ei, E, ET, N);
    {
        long long threads = (long long)N * 32;
        int blocks = (int)((threads + 255) / 256);
        k_agg<<<blocks, 256>>>(out, N);
    }
}